// round 14
// baseline (speedup 1.0000x reference)
#include <cuda_runtime.h>
#include <cuda_bf16.h>
#include <math.h>
#include <stdint.h>

#define NB 16
#define PADPIX 256
#define GEMM_HDR 1024
#define STAGE_BYTES 98304  // Ahi16K+Alo16K+Bhi32K+Blo32K
#define GEMM_SMEM (GEMM_HDR + 2 * STAGE_BYTES)

// tcgen05 is arch-SPECIFIC: only emit it on the sm_103a/f pass, not compute_103.
#if (defined(__CUDA_ARCH_SPECIFIC__) && (__CUDA_ARCH_SPECIFIC__ == 1030)) || \
    (defined(__CUDA_ARCH_FAMILY_SPECIFIC__) && (__CUDA_ARCH_FAMILY_SPECIFIC__ == 1030))
#define HAS_TCGEN05 1
#else
#define HAS_TCGEN05 0
#endif

__device__ float g_c1 [4194304];
__device__ float g_c2 [4194304];
__device__ float g_c3 [4194304];
__device__ float g_w4 [4194304];
__device__ float g_t0 [4194304];
__device__ float g_t1 [4194304];
__device__ float g_big[8388608];
__device__ float g_wsw[9437184];
__device__ float g_part[16384];
__device__ float g_mstats[4096];
__device__ __align__(1024) __nv_bfloat16 g_xhi[12582912];
__device__ __align__(1024) __nv_bfloat16 g_xlo[12582912];
__device__ __align__(1024) __nv_bfloat16 g_xh2[10000000];  // convd4 concat [c3|iwt(ic4)], 512-wide
__device__ __align__(1024) __nv_bfloat16 g_xl2[10000000];
__device__ __align__(1024) __nv_bfloat16 g_xh3[9100000];   // convd3 concat [c2|iwt(ic3)], 128-wide
__device__ __align__(1024) __nv_bfloat16 g_xl3[9100000];
__device__ __align__(1024) __nv_bfloat16 g_whi[9437184];
__device__ __align__(1024) __nv_bfloat16 g_wlo[9437184];

// ---------------- PTX helpers ----------------
__device__ __forceinline__ uint32_t smem_u32(const void* p) {
    uint32_t a;
    asm("{ .reg .u64 t; cvta.to.shared.u64 t, %1; cvt.u32.u64 %0, t; }" : "=r"(a) : "l"(p));
    return a;
}
__device__ __forceinline__ uint32_t elect_one() {
    uint32_t p;
    asm volatile("{\n\t.reg .pred p;\n\telect.sync _|p, 0xFFFFFFFF;\n\tselp.b32 %0, 1, 0, p;\n\t}" : "=r"(p));
    return p;
}
#define SWZ(off) ((off) ^ (((off) >> 3) & 0x70))
static constexpr uint64_t DESC_BASE =
    (uint64_t(2) << 61) | (uint64_t(1) << 46) | (uint64_t(64) << 32) | (uint64_t(1) << 16);
#define MK_DESC(a) (DESC_BASE | ((uint64_t)((a) >> 4) & 0x3FFF))

#define MBAR_INIT(a, c) asm volatile("mbarrier.init.shared.b64 [%0], %1;" :: "r"((uint32_t)(a)), "r"((uint32_t)(c)) : "memory")
#define MBAR_INVAL(a)   asm volatile("mbarrier.inval.shared.b64 [%0];" :: "r"((uint32_t)(a)) : "memory")
#define MBAR_WAIT(a, par) do { \
    uint32_t _m = (uint32_t)(a), _p = (uint32_t)(par), _d; \
    asm volatile("{\n\t.reg .pred p;\n\tmbarrier.try_wait.parity.acquire.cta.shared::cta.b64 p, [%1], %2;\n\tselp.b32 %0, 1, 0, p;\n\t}" \
        : "=r"(_d) : "r"(_m), "r"(_p) : "memory"); \
    if (!_d) { \
        asm volatile("{\n\t.reg .pred P1;\n\tWL_%=:\n\tmbarrier.try_wait.parity.acquire.cta.shared::cta.b64 P1, [%0], %1, 0x989680;\n\t@P1 bra.uni WD_%=;\n\tbra.uni WL_%=;\n\tWD_%=:\n\t}" \
            :: "r"(_m), "r"(_p) : "memory"); \
    } } while (0)

__device__ __forceinline__ void cp16(uint32_t dst, const void* src) {
    asm volatile("cp.async.cg.shared.global [%0], [%1], 16;" :: "r"(dst), "l"(src));
}

#if HAS_TCGEN05
#define TC_ALLOC(sa, n)  asm volatile("tcgen05.alloc.cta_group::1.sync.aligned.shared::cta.b32 [%0], %1;" :: "r"((uint32_t)(sa)), "r"((uint32_t)(n)) : "memory")
#define TC_DEALLOC(t, n) asm volatile("tcgen05.dealloc.cta_group::1.sync.aligned.b32 %0, %1;" :: "r"(t), "r"((uint32_t)(n)))
#define TC_COMMIT(mb)    asm volatile("tcgen05.commit.cta_group::1.mbarrier::arrive::one.shared::cluster.b64 [%0];" :: "r"((uint32_t)(mb)) : "memory")
#define TC_FENCE_AFTER()  asm volatile("tcgen05.fence::after_thread_sync;" ::: "memory")
#define TC_FENCE_BEFORE() asm volatile("tcgen05.fence::before_thread_sync;" ::: "memory")
#define TC_WAIT_LD()      asm volatile("tcgen05.wait::ld.sync.aligned;" ::: "memory")
#define FENCE_ASYNC()     asm volatile("fence.proxy.async.shared::cta;" ::: "memory")

#define TC_LD_X32(r, ta) \
    asm volatile("tcgen05.ld.sync.aligned.32x32b.x32.b32 " \
        "{%0,%1,%2,%3,%4,%5,%6,%7,%8,%9,%10,%11,%12,%13,%14,%15," \
        "%16,%17,%18,%19,%20,%21,%22,%23,%24,%25,%26,%27,%28,%29,%30,%31}, [%32];" \
        : "=r"((r)[0]),"=r"((r)[1]),"=r"((r)[2]),"=r"((r)[3]),"=r"((r)[4]),"=r"((r)[5]),"=r"((r)[6]),"=r"((r)[7]), \
          "=r"((r)[8]),"=r"((r)[9]),"=r"((r)[10]),"=r"((r)[11]),"=r"((r)[12]),"=r"((r)[13]),"=r"((r)[14]),"=r"((r)[15]), \
          "=r"((r)[16]),"=r"((r)[17]),"=r"((r)[18]),"=r"((r)[19]),"=r"((r)[20]),"=r"((r)[21]),"=r"((r)[22]),"=r"((r)[23]), \
          "=r"((r)[24]),"=r"((r)[25]),"=r"((r)[26]),"=r"((r)[27]),"=r"((r)[28]),"=r"((r)[29]),"=r"((r)[30]),"=r"((r)[31]) \
        : "r"(ta))

__device__ __forceinline__ void mma_ss(uint32_t d, uint64_t a, uint64_t b, uint32_t idesc, uint32_t acc) {
    asm volatile(
        "{\n\t.reg .pred p;\n\tsetp.ne.u32 p, %5, 0;\n\t"
        "tcgen05.mma.cta_group::1.kind::f16 [%0], %1, %2, %3, {%4, %4, %4, %4}, p;\n\t}"
        :: "r"(d), "l"(a), "l"(b), "r"(idesc), "r"(0u), "r"(acc) : "memory");
}
#define MMA_IDESC 0x8400490u  // f32 acc, bf16 x bf16, M=128, N=256
#endif // HAS_TCGEN05

// ---------------- pack kernels ----------------
__device__ __forceinline__ void store_hilo(__nv_bfloat16* hi, __nv_bfloat16* lo,
                                           size_t idx, float v) {
    __nv_bfloat16 h = __float2bfloat16(v);
    hi[idx] = h;
    lo[idx] = __float2bfloat16(v - __bfloat162float(h));
}

__global__ void pack_gn_x_kernel(const float* __restrict__ src,
                                 __nv_bfloat16* __restrict__ hi, __nv_bfloat16* __restrict__ lo,
                                 int Csrc, int c_off, int Cdst, int H, int W,
                                 const float* __restrict__ gamma, const float* __restrict__ beta,
                                 int G)
{
    __shared__ float tile[32][33];
    int n = blockIdx.z;
    int c0 = blockIdx.y * 32;
    int p0 = blockIdx.x * 32;
    int HW = H * W;
    for (int cc = threadIdx.y; cc < 32; cc += 8)
        tile[cc][threadIdx.x] = src[((size_t)(n * Csrc + c0 + cc)) * HW + p0 + threadIdx.x];
    __syncthreads();
    int c = c0 + threadIdx.x;
    float sc = 1.f, sh = 0.f;
    if (gamma) {
        int cpg = Csrc / G;
        int ng = n * G + c / cpg;
        float mean = g_mstats[ng * 2], inv = g_mstats[ng * 2 + 1];
        sc = inv * gamma[c];
        sh = beta[c] - mean * sc;
    }
    int Wp = W + 2, HpWp = (H + 2) * Wp;
    for (int pp = threadIdx.y; pp < 32; pp += 8) {
        int p = p0 + pp; int y = p / W, x = p - y * W;
        size_t row = (size_t)n * HpWp + (size_t)(y + 1) * Wp + (x + 1);
        float v = tile[threadIdx.x][pp] * sc + sh;
        store_hilo(hi, lo, row * Cdst + c_off + c, v);
    }
}

// Haar inverse straight into packed bf16, with optional fused GroupNorm on the
// 4C-channel input tensor (applied BEFORE the detail remap, matching gn->iwt).
__global__ void iwt_pack_kernel(const float* __restrict__ in,
                                __nv_bfloat16* __restrict__ hi, __nv_bfloat16* __restrict__ lo,
                                int C, int h, int w, int c_off, int Cdst,
                                const float* __restrict__ gamma, const float* __restrict__ beta,
                                int G)
{
    __shared__ float tile[4][32][33];
    int n = blockIdx.z;
    int c0 = blockIdx.y * 32;
    int p0 = blockIdx.x * 32;
    int hw = h * w;
    int C4 = 4 * C, cpg = gamma ? (C4 / G) : 1;
    for (int k = 0; k < 4; k++)
        for (int cc = threadIdx.y; cc < 32; cc += 8) {
            int ch = 4 * (c0 + cc) + k;
            float v = in[((size_t)(n * C4 + ch)) * hw + p0 + threadIdx.x];
            if (gamma) {
                int ng = n * G + ch / cpg;
                float mean = g_mstats[ng * 2], inv = g_mstats[ng * 2 + 1];
                v = (v - mean) * inv * gamma[ch] + beta[ch];
            }
            tile[k][cc][threadIdx.x] = v;
        }
    __syncthreads();
    int c = c_off + c0 + threadIdx.x;
    int Wp = 2 * w + 2, HpWp = (2 * h + 2) * Wp;
    for (int pp = threadIdx.y; pp < 32; pp += 8) {
        int p = p0 + pp; int i = p / w, j = p - i * w;
        float s0 = tile[0][threadIdx.x][pp];
        float s1 = 2.f * tile[1][threadIdx.x][pp] - 1.f;
        float s2 = 2.f * tile[2][threadIdx.x][pp] - 1.f;
        float s3 = 2.f * tile[3][threadIdx.x][pp] - 1.f;
        size_t r00 = (size_t)n * HpWp + (size_t)(2 * i + 1) * Wp + (2 * j + 1);
        store_hilo(hi, lo, r00 * Cdst + c,            s0 + 0.5f * ( s1 + s2 + s3));
        store_hilo(hi, lo, (r00 + 1) * Cdst + c,      s0 + 0.5f * ( s1 - s2 - s3));
        store_hilo(hi, lo, (r00 + Wp) * Cdst + c,     s0 + 0.5f * (-s1 + s2 - s3));
        store_hilo(hi, lo, (r00 + Wp + 1) * Cdst + c, s0 + 0.5f * (-s1 - s2 + s3));
    }
}

__global__ void ws_pack_kernel(const float* __restrict__ w,
                               __nv_bfloat16* __restrict__ hi, __nv_bfloat16* __restrict__ lo,
                               int Cin, int Cout)
{
    int f = blockIdx.x;
    int K = Cin * 9;
    const float* wf = w + (size_t)f * K;
    __shared__ float red[256];
    float s = 0.f;
    for (int i = threadIdx.x; i < K; i += 256) s += wf[i];
    red[threadIdx.x] = s; __syncthreads();
    for (int o = 128; o; o >>= 1) { if (threadIdx.x < o) red[threadIdx.x] += red[threadIdx.x + o]; __syncthreads(); }
    float mean = red[0] / (float)K;
    __syncthreads();
    float ss = 0.f;
    for (int i = threadIdx.x; i < K; i += 256) { float d = wf[i] - mean; ss += d * d; }
    red[threadIdx.x] = ss; __syncthreads();
    for (int o = 128; o; o >>= 1) { if (threadIdx.x < o) red[threadIdx.x] += red[threadIdx.x + o]; __syncthreads(); }
    float inv = 1.0f / (sqrtf(red[0] / (float)(K - 1)) + 1e-5f);
    for (int i = threadIdx.x; i < K; i += 256) {
        int ci = i / 9, tap = i - ci * 9;
        float v = (wf[i] - mean) * inv;
        store_hilo(hi, lo, (size_t)(tap * Cout + f) * Cin + ci, v);
    }
}

// Fused: optional GroupNorm (per-channel affine from g_mstats; optional in-place
// fp32 writeback via `normed`; optional secondary packed output of the NORMALIZED
// input at its own resolution/layout) -> Haar forward -> bf16 hi/lo pack
// (+ optional fp32 wt out).
__global__ void wt_pack_kernel(const float* __restrict__ in, float* __restrict__ normed,
                               float* __restrict__ outf,
                               __nv_bfloat16* __restrict__ hi, __nv_bfloat16* __restrict__ lo,
                               int C, int H, int W,
                               const float* __restrict__ gamma, const float* __restrict__ beta,
                               int G,
                               __nv_bfloat16* __restrict__ hi2, __nv_bfloat16* __restrict__ lo2,
                               int c_off2, int Cdst2)
{
    int h2 = H >> 1, w2 = W >> 1;
    int C4 = 4 * C;
    int Wp = w2 + 2, HpWp = (h2 + 2) * Wp;
    int Wp2 = W + 2, HpWp2 = (H + 2) * Wp2;
    int cpg = gamma ? (C / G) : 1;
    size_t total = (size_t)NB * C * h2 * w2;
    for (size_t idx = (size_t)blockIdx.x * blockDim.x + threadIdx.x; idx < total;
         idx += (size_t)gridDim.x * blockDim.x) {
        int j = (int)(idx % w2); size_t t = idx / w2;
        int i = (int)(t % h2); t /= h2;
        int c = (int)(t % C); int n = (int)(t / C);
        size_t pb = ((size_t)(n * C + c) * H + 2 * i) * W + 2 * j;
        const float* p = in + pb;
        float a = p[0], b = p[1], cc = p[W], d = p[W + 1];
        if (gamma) {
            int ng = n * G + c / cpg;
            float mean = g_mstats[ng * 2], inv = g_mstats[ng * 2 + 1];
            float sc = inv * gamma[c], sh = beta[c] - mean * sc;
            a = a * sc + sh; b = b * sc + sh; cc = cc * sc + sh; d = d * sc + sh;
            if (normed) {
                float* q = normed + pb;
                q[0] = a; q[1] = b; q[W] = cc; q[W + 1] = d;
            }
        }
        if (hi2) {
            size_t r = (size_t)n * HpWp2 + (size_t)(2 * i + 1) * Wp2 + (2 * j + 1);
            size_t cidx = (size_t)c_off2 + c;
            store_hilo(hi2, lo2, r * Cdst2 + cidx, a);
            store_hilo(hi2, lo2, (r + 1) * Cdst2 + cidx, b);
            store_hilo(hi2, lo2, (r + Wp2) * Cdst2 + cidx, cc);
            store_hilo(hi2, lo2, (r + Wp2 + 1) * Cdst2 + cidx, d);
        }
        float v0 = 0.25f * (a + b + cc + d);
        float v1 = 0.25f * (a + b - cc - d) + 0.5f;
        float v2 = 0.25f * (a - b + cc - d) + 0.5f;
        float v3 = 0.25f * (a - b - cc + d) + 0.5f;
        if (outf) {
            size_t cs = (size_t)h2 * w2;
            size_t ob = (((size_t)n * C4 + 4 * c) * h2 + i) * w2 + j;
            outf[ob] = v0; outf[ob + cs] = v1; outf[ob + 2 * cs] = v2; outf[ob + 3 * cs] = v3;
        }
        size_t row = (size_t)n * HpWp + (size_t)(i + 1) * Wp + (j + 1);
        size_t base = row * C4 + 4 * c;
        store_hilo(hi, lo, base + 0, v0);
        store_hilo(hi, lo, base + 1, v1);
        store_hilo(hi, lo, base + 2, v2);
        store_hilo(hi, lo, base + 3, v3);
    }
}

// ---------------- tcgen05 conv (implicit GEMM, 3-pass bf16 hi/lo) ----------------
__global__ void __launch_bounds__(256, 1) conv_mma_kernel(
    const __nv_bfloat16* __restrict__ Whi, const __nv_bfloat16* __restrict__ Wlo,
    const __nv_bfloat16* __restrict__ Xhi, const __nv_bfloat16* __restrict__ Xlo,
    const float* __restrict__ bias, const float* __restrict__ skip,
    float* __restrict__ out, int Cin, int Cout, int H, int W, int do_lrelu)
{
#if HAS_TCGEN05
    extern __shared__ char smem[];
    uint32_t sb = smem_u32(smem);
    int tid = threadIdx.x, wid = tid >> 5, lane = tid & 31;
    int Wp = W + 2, HpWp = (H + 2) * Wp;
    int Np = NB * HpWp;
    int px_base = blockIdx.x * 256;
    int co_base = blockIdx.y * 128;
    int kchunks = Cin >> 6;
    int n_chunks = 9 * kchunks;

    if (wid == 0) TC_ALLOC(sb + 0, 256);
    if (tid == 0) { MBAR_INIT(sb + 16, 1); MBAR_INIT(sb + 24, 1); }
    __syncthreads();
    uint32_t tmem;
    asm volatile("ld.shared.b32 %0, [%1];" : "=r"(tmem) : "r"(sb + 0));

    int r0 = tid >> 3, g = tid & 7;

    auto load_chunk = [&](int i) {
        uint32_t stage = sb + GEMM_HDR + (i & 1) * STAGE_BYTES;
        int tap = i / kchunks, kc = i - tap * kchunks;
        int shift = (tap / 3 - 1) * Wp + (tap % 3 - 1);
        const __nv_bfloat16* ah = Whi + (size_t)(tap * Cout + co_base) * Cin + kc * 64;
        const __nv_bfloat16* al = Wlo + (size_t)(tap * Cout + co_base) * Cin + kc * 64;
        const __nv_bfloat16* bh = Xhi + (size_t)(px_base + shift) * Cin + kc * 64;
        const __nv_bfloat16* bl = Xlo + (size_t)(px_base + shift) * Cin + kc * 64;
#pragma unroll
        for (int j = 0; j < 4; j++) {
            int row = r0 + 32 * j;
            uint32_t d = SWZ((uint32_t)(row * 128 + g * 16));
            cp16(stage + 0     + d, ah + (size_t)row * Cin + g * 8);
            cp16(stage + 16384 + d, al + (size_t)row * Cin + g * 8);
        }
#pragma unroll
        for (int j = 0; j < 8; j++) {
            int row = r0 + 32 * j;
            uint32_t d = SWZ((uint32_t)(row * 128 + g * 16));
            cp16(stage + 32768 + d, bh + (size_t)row * Cin + g * 8);
            cp16(stage + 65536 + d, bl + (size_t)row * Cin + g * 8);
        }
        asm volatile("cp.async.commit_group;" ::: "memory");
    };

    load_chunk(0);
    for (int i = 0; i < n_chunks; i++) {
        if (i + 1 < n_chunks) {
            if (i >= 1) MBAR_WAIT(sb + 16 + 8 * ((i + 1) & 1), ((i - 1) >> 1) & 1);
            load_chunk(i + 1);
            asm volatile("cp.async.wait_group 1;" ::: "memory");
        } else {
            asm volatile("cp.async.wait_group 0;" ::: "memory");
        }
        __syncthreads();
        if (wid == 0 && elect_one()) {
            FENCE_ASYNC();
            uint32_t stage = sb + GEMM_HDR + (i & 1) * STAGE_BYTES;
            uint64_t dAh = MK_DESC(stage), dAl = MK_DESC(stage + 16384);
            uint64_t dBh = MK_DESC(stage + 32768), dBl = MK_DESC(stage + 65536);
#pragma unroll
            for (int k = 0; k < 4; k++)
                mma_ss(tmem, dAh + 2 * k, dBh + 2 * k, MMA_IDESC, (i != 0 || k != 0) ? 1u : 0u);
#pragma unroll
            for (int k = 0; k < 4; k++)
                mma_ss(tmem, dAl + 2 * k, dBh + 2 * k, MMA_IDESC, 1u);
#pragma unroll
            for (int k = 0; k < 4; k++)
                mma_ss(tmem, dAh + 2 * k, dBl + 2 * k, MMA_IDESC, 1u);
            TC_COMMIT(sb + 16 + 8 * (i & 1));
        }
    }
    {
        int uses0 = (n_chunks + 1) >> 1, uses1 = n_chunks >> 1;
        MBAR_WAIT(sb + 16, (uses0 - 1) & 1);
        if (uses1 > 0) MBAR_WAIT(sb + 24, (uses1 - 1) & 1);
    }
    TC_FENCE_AFTER();

    // epilogue: warp w -> subpartition w&3; half w>>2 covers 4 of 8 col-blocks
    float* tsm = reinterpret_cast<float*>(smem + GEMM_HDR) + wid * (32 * 33);
    int HW = H * W;
    int sub = wid & 3, half = wid >> 2;
    float bl_lane = (co_base + sub * 32 + lane < Cout) ? bias[co_base + sub * 32 + lane] : 0.f;
    for (int cb2 = half * 4; cb2 < half * 4 + 4; cb2++) {
        uint32_t regs[32];
        TC_LD_X32(regs, tmem + cb2 * 32);
        TC_WAIT_LD();
#pragma unroll
        for (int c = 0; c < 32; c++) tsm[c * 33 + lane] = __uint_as_float(regs[c]);
        __syncwarp();
        int p = px_base + cb2 * 32 + lane;
        int valid = 0; size_t obase = 0;
        if (p < Np) {
            int n = p / HpWp; int rem = p - n * HpWp;
            int yp = rem / Wp; int xp = rem - yp * Wp;
            if ((unsigned)(yp - 1) < (unsigned)H && (unsigned)(xp - 1) < (unsigned)W) {
                valid = 1;
                obase = ((size_t)n * Cout * H + (yp - 1)) * W + (xp - 1);
            }
        }
#pragma unroll
        for (int r = 0; r < 32; r++) {
            int co = co_base + sub * 32 + r;
            float bv = __shfl_sync(0xFFFFFFFFu, bl_lane, r);
            if (co < Cout && valid) {
                float v = tsm[lane * 33 + r] + bv;
                size_t o = obase + (size_t)co * HW;
                if (skip) v += skip[o];
                if (do_lrelu) v = v > 0.f ? v : 0.2f * v;
                out[o] = v;
            }
        }
        __syncwarp();
    }
    TC_FENCE_BEFORE();
    __syncthreads();
    if (tid == 0) { MBAR_INVAL(sb + 16); MBAR_INVAL(sb + 24); }
    __syncthreads();
    if (wid == 0) TC_DEALLOC(tmem, 256);
#endif // HAS_TCGEN05
}

// ---------------- fp32 helper kernels ----------------
__global__ void ws_kernel(const float* __restrict__ w, float* __restrict__ out, int K)
{
    int f = blockIdx.x;
    const float* wf = w + (size_t)f * K;
    __shared__ float red[256];
    float s = 0.f;
    for (int i = threadIdx.x; i < K; i += 256) s += wf[i];
    red[threadIdx.x] = s; __syncthreads();
    for (int o = 128; o; o >>= 1) { if (threadIdx.x < o) red[threadIdx.x] += red[threadIdx.x + o]; __syncthreads(); }
    float mean = red[0] / (float)K;
    __syncthreads();
    float ss = 0.f;
    for (int i = threadIdx.x; i < K; i += 256) { float d = wf[i] - mean; ss += d * d; }
    red[threadIdx.x] = ss; __syncthreads();
    for (int o = 128; o; o >>= 1) { if (threadIdx.x < o) red[threadIdx.x] += red[threadIdx.x + o]; __syncthreads(); }
    float inv = 1.0f / (sqrtf(red[0] / (float)(K - 1)) + 1e-5f);
    for (int i = threadIdx.x; i < K; i += 256)
        out[(size_t)f * K + i] = (wf[i] - mean) * inv;
}

// S==1: finalize stats directly into g_mstats (skips the reduce launch).
__global__ void gn_stats_kernel(const float* __restrict__ x, int C, int HW, int G, int S)
{
    int gid = blockIdx.x;
    int ng = gid / S, sl = gid - (gid / S) * S;
    int n = ng / G, grp = ng % G;
    int cpg = C / G;
    int len = cpg * HW;
    int slice = (len + S - 1) / S;
    int start = sl * slice;
    int end = start + slice; if (end > len) end = len;
    size_t base = ((size_t)n * C + (size_t)grp * cpg) * HW;
    __shared__ float r1[256], r2[256];
    float s = 0.f, ss = 0.f;
    for (int i = start + threadIdx.x; i < end; i += 256) {
        float v = x[base + i]; s += v; ss += v * v;
    }
    r1[threadIdx.x] = s; r2[threadIdx.x] = ss; __syncthreads();
    for (int o = 128; o; o >>= 1) {
        if (threadIdx.x < o) { r1[threadIdx.x] += r1[threadIdx.x + o]; r2[threadIdx.x] += r2[threadIdx.x + o]; }
        __syncthreads();
    }
    if (threadIdx.x == 0) {
        if (S == 1) {
            float mean = r1[0] / (float)len;
            float var  = r2[0] / (float)len - mean * mean;
            g_mstats[ng * 2] = mean;
            g_mstats[ng * 2 + 1] = rsqrtf(var + 1e-5f);
        } else {
            g_part[gid * 2] = r1[0]; g_part[gid * 2 + 1] = r2[0];
        }
    }
}
__global__ void gn_reduce_kernel(int S, int len)
{
    int ng = blockIdx.x;
    float s = 0.f, ss = 0.f;
    for (int i = threadIdx.x; i < S; i += 32) {
        s  += g_part[(ng * S + i) * 2];
        ss += g_part[(ng * S + i) * 2 + 1];
    }
    for (int o = 16; o; o >>= 1) {
        s  += __shfl_down_sync(0xFFFFFFFFu, s, o);
        ss += __shfl_down_sync(0xFFFFFFFFu, ss, o);
    }
    if (threadIdx.x == 0) {
        float mean = s / (float)len;
        float var  = ss / (float)len - mean * mean;
        g_mstats[ng * 2] = mean;
        g_mstats[ng * 2 + 1] = rsqrtf(var + 1e-5f);
    }
}

__global__ void wt_kernel(const float* __restrict__ in, float* __restrict__ out, int C, int H, int W)
{
    int h2 = H >> 1, w2 = W >> 1;
    size_t total = (size_t)NB * C * h2 * w2;
    for (size_t idx = (size_t)blockIdx.x * blockDim.x + threadIdx.x; idx < total;
         idx += (size_t)gridDim.x * blockDim.x) {
        int j = (int)(idx % w2); size_t t = idx / w2;
        int i = (int)(t % h2); t /= h2;
        int c = (int)(t % C); int n = (int)(t / C);
        const float* p = in + ((size_t)(n * C + c) * H + 2 * i) * W + 2 * j;
        float a = p[0], b = p[1], cc = p[W], d = p[W + 1];
        size_t cs = (size_t)h2 * w2;
        size_t ob = (((size_t)n * 4 * C + 4 * c) * h2 + i) * w2 + j;
        out[ob]          = 0.25f * (a + b + cc + d);
        out[ob + cs]     = 0.25f * (a + b - cc - d) + 0.5f;
        out[ob + 2 * cs] = 0.25f * (a - b + cc - d) + 0.5f;
        out[ob + 3 * cs] = 0.25f * (a - b - cc + d) + 0.5f;
    }
}

// fp32 Haar inverse with optional fused GroupNorm on the 4C-channel input.
__global__ void iwt_kernel(const float* __restrict__ in, float* __restrict__ out,
                           int C, int h, int w, int c_off, int Cdst,
                           const float* __restrict__ gamma, const float* __restrict__ beta,
                           int G)
{
    size_t total = (size_t)NB * C * h * w;
    int C4 = 4 * C, cpg = gamma ? (C4 / G) : 1;
    for (size_t idx = (size_t)blockIdx.x * blockDim.x + threadIdx.x; idx < total;
         idx += (size_t)gridDim.x * blockDim.x) {
        int j = (int)(idx % w); size_t t = idx / w;
        int i = (int)(t % h); t /= h;
        int c = (int)(t % C); int n = (int)(t / C);
        size_t cs = (size_t)h * w;
        size_t ib = (((size_t)n * C4 + 4 * c) * h + i) * w + j;
        float sv[4];
#pragma unroll
        for (int k = 0; k < 4; k++) {
            float v = in[ib + k * cs];
            if (gamma) {
                int ch = 4 * c + k;
                int ng = n * G + ch / cpg;
                float mean = g_mstats[ng * 2], inv = g_mstats[ng * 2 + 1];
                v = (v - mean) * inv * gamma[ch] + beta[ch];
            }
            sv[k] = v;
        }
        float s0 = sv[0];
        float s1 = 2.f * sv[1] - 1.f;
        float s2 = 2.f * sv[2] - 1.f;
        float s3 = 2.f * sv[3] - 1.f;
        float* q = out + (((size_t)n * Cdst + c_off + c) * 2 * h + 2 * i) * 2 * w + 2 * j;
        q[0]         = s0 + 0.5f * ( s1 + s2 + s3);
        q[1]         = s0 + 0.5f * ( s1 - s2 - s3);
        q[2 * w]     = s0 + 0.5f * (-s1 + s2 - s3);
        q[2 * w + 1] = s0 + 0.5f * (-s1 - s2 + s3);
    }
}

__global__ void copy_ch_kernel(const float* __restrict__ src, float* __restrict__ dst,
                               int C, int HW, int Cdst, int c_off)
{
    size_t total = (size_t)NB * C * HW;
    for (size_t idx = (size_t)blockIdx.x * blockDim.x + threadIdx.x; idx < total;
         idx += (size_t)gridDim.x * blockDim.x) {
        int p = (int)(idx % HW); size_t t = idx / HW;
        int c = (int)(t % C); int n = (int)(t / C);
        dst[((size_t)n * Cdst + c_off + c) * HW + p] = src[idx];
    }
}

// fp32 direct conv, 16-co tile; optional fused GroupNorm affine on the INPUT.
__global__ __launch_bounds__(256) void conv3x3_c16_kernel(
    const float* __restrict__ in, const float* __restrict__ wgt,
    const float* __restrict__ bias, const float* __restrict__ skip,
    float* __restrict__ out, int Cin, int Cout, int H, int W, int do_lrelu,
    const float* __restrict__ gamma, const float* __restrict__ beta, int G)
{
    __shared__ __align__(16) float s_in[4][18][18];
    __shared__ __align__(16) float s_w[4][9][16];
    int tiles_x = W >> 4;
    int tx0 = (blockIdx.x % tiles_x) << 4;
    int ty0 = (blockIdx.x / tiles_x) << 4;
    int n = blockIdx.z;
    int tx = threadIdx.x;
    int cog8 = (tx >> 7) << 3;
    int pid  = tx & 127;
    int prow = pid >> 3;
    int pcol = (pid & 7) << 1;
    int cpg = gamma ? (Cin / G) : 1;

    float acc[8][2];
#pragma unroll
    for (int r = 0; r < 8; r++) { acc[r][0] = 0.f; acc[r][1] = 0.f; }

    for (int cc = 0; cc < Cin; cc += 4) {
        for (int idx = tx; idx < 4 * 9 * 16; idx += 256) {
            int co = idx & 15;
            int tap = (idx >> 4) % 9;
            int ci = (idx >> 4) / 9;
            float v = 0.f;
            if (co < Cout && cc + ci < Cin)
                v = wgt[((size_t)co * Cin + cc + ci) * 9 + tap];
            s_w[ci][tap][co] = v;
        }
        for (int idx = tx; idx < 4 * 18 * 18; idx += 256) {
            int ix = idx % 18; int t = idx / 18;
            int iy = t % 18;  int ci = t / 18;
            int gy = ty0 + iy - 1, gx = tx0 + ix - 1;
            float v = 0.f;
            if (cc + ci < Cin && gy >= 0 && gy < H && gx >= 0 && gx < W) {
                v = in[((size_t)(n * Cin + cc + ci) * H + gy) * W + gx];
                if (gamma) {
                    int ch = cc + ci;
                    int ng = n * G + ch / cpg;
                    float mean = g_mstats[ng * 2], inv = g_mstats[ng * 2 + 1];
                    v = (v - mean) * inv * gamma[ch] + beta[ch];
                }
            }
            s_in[ci][iy][ix] = v;
        }
        __syncthreads();
#pragma unroll
        for (int ci = 0; ci < 4; ci++)
#pragma unroll
            for (int dy = 0; dy < 3; dy++)
#pragma unroll
                for (int dx = 0; dx < 3; dx++) {
                    float x0 = s_in[ci][prow + dy][pcol + dx];
                    float x1 = s_in[ci][prow + dy][pcol + dx + 1];
                    const float* wp = &s_w[ci][dy * 3 + dx][cog8];
                    float4 wa = *reinterpret_cast<const float4*>(wp);
                    float4 wb = *reinterpret_cast<const float4*>(wp + 4);
                    float wv[8] = {wa.x, wa.y, wa.z, wa.w, wb.x, wb.y, wb.z, wb.w};
#pragma unroll
                    for (int r = 0; r < 8; r++) {
                        acc[r][0] = fmaf(wv[r], x0, acc[r][0]);
                        acc[r][1] = fmaf(wv[r], x1, acc[r][1]);
                    }
                }
        __syncthreads();
    }
    int oy = ty0 + prow;
#pragma unroll
    for (int r = 0; r < 8; r++) {
        int co = cog8 + r;
        if (co < Cout) {
            float b = bias ? bias[co] : 0.f;
            size_t ob = ((size_t)(n * Cout + co) * H + oy) * W + tx0 + pcol;
#pragma unroll
            for (int p = 0; p < 2; p++) {
                float v = acc[r][p] + b;
                if (skip) v += skip[ob + p];
                if (do_lrelu) v = v > 0.f ? v : 0.2f * v;
                out[ob + p] = v;
            }
        }
    }
}

__global__ void final_kernel(const float* __restrict__ in, const float* __restrict__ w,
                             float* __restrict__ out, int HW)
{
    size_t total = (size_t)NB * HW;
    for (size_t idx = (size_t)blockIdx.x * blockDim.x + threadIdx.x; idx < total;
         idx += (size_t)gridDim.x * blockDim.x) {
        int p = (int)(idx % HW); int n = (int)(idx / HW);
        const float* ip = in + (size_t)n * 3 * HW + p;
        float x0 = ip[0], x1 = ip[HW], x2 = ip[2 * HW];
        float* op = out + (size_t)n * 2 * HW + p;
        op[0]  = w[0] * x0 + w[1] * x1 + w[2] * x2;
        op[HW] = w[3] * x0 + w[4] * x1 + w[5] * x2;
    }
}

// ---------------- host ----------------
static inline int blocks_for(size_t n) { return (int)((n + 255) / 256); }

extern "C" void kernel_launch(void* const* d_in, const int* in_sizes, int n_in,
                              void* d_out, int out_size)
{
    const float* x        = (const float*)d_in[0];
    const float* conv1_w  = (const float*)d_in[1];  const float* conv1_b  = (const float*)d_in[2];
    const float* conv2_w  = (const float*)d_in[3];  const float* conv2_b  = (const float*)d_in[4];
    const float* conv3_w  = (const float*)d_in[5];  const float* conv3_b  = (const float*)d_in[6];
    const float* conv4_w  = (const float*)d_in[7];  const float* conv4_b  = (const float*)d_in[8];
    const float* convd1_w = (const float*)d_in[9];  const float* convd1_b = (const float*)d_in[10];
    const float* convd2_w = (const float*)d_in[11]; const float* convd2_b = (const float*)d_in[12];
    const float* convd3_w = (const float*)d_in[13]; const float* convd3_b = (const float*)d_in[14];
    const float* convd4_w = (const float*)d_in[15]; const float* convd4_b = (const float*)d_in[16];
    const float* final_w  = (const float*)d_in[17];
    const float* gn1_w = (const float*)d_in[18]; const float* gn1_b = (const float*)d_in[19];
    const float* gn2_w = (const float*)d_in[20]; const float* gn2_b = (const float*)d_in[21];
    const float* gn3_w = (const float*)d_in[22]; const float* gn3_b = (const float*)d_in[23];
    const float* gn4_w = (const float*)d_in[24]; const float* gn4_b = (const float*)d_in[25];

    float *c1, *c2, *c3, *w4, *t0, *t1, *big, *wsw;
    __nv_bfloat16 *xhi, *xlo, *xh2, *xl2, *xh3, *xl3, *whi, *wlo;
    cudaGetSymbolAddress((void**)&c1,  g_c1);
    cudaGetSymbolAddress((void**)&c2,  g_c2);
    cudaGetSymbolAddress((void**)&c3,  g_c3);
    cudaGetSymbolAddress((void**)&w4,  g_w4);
    cudaGetSymbolAddress((void**)&t0,  g_t0);
    cudaGetSymbolAddress((void**)&t1,  g_t1);
    cudaGetSymbolAddress((void**)&big, g_big);
    cudaGetSymbolAddress((void**)&wsw, g_wsw);
    cudaGetSymbolAddress((void**)&xhi, g_xhi);
    cudaGetSymbolAddress((void**)&xlo, g_xlo);
    cudaGetSymbolAddress((void**)&xh2, g_xh2);
    cudaGetSymbolAddress((void**)&xl2, g_xl2);
    cudaGetSymbolAddress((void**)&xh3, g_xh3);
    cudaGetSymbolAddress((void**)&xl3, g_xl3);
    cudaGetSymbolAddress((void**)&whi, g_whi);
    cudaGetSymbolAddress((void**)&wlo, g_wlo);

    cudaFuncSetAttribute(conv_mma_kernel, cudaFuncAttributeMaxDynamicSharedMemorySize, GEMM_SMEM);

    auto ntiles_of = [](int H, int W) { return (NB * (H + 2) * (W + 2) + 255) / 256; };
    auto prep_w = [&](const float* w, int Cin, int Cout) {
        ws_pack_kernel<<<Cout, 256>>>(w, whi, wlo, Cin, Cout);
    };
    auto clear_x = [&](int Cin, int H, int W) {
        size_t xb = (size_t)(2 * PADPIX + ntiles_of(H, W) * 256) * Cin * sizeof(__nv_bfloat16);
        cudaMemsetAsync(xhi, 0, xb);
        cudaMemsetAsync(xlo, 0, xb);
    };
    auto pack_gn = [&](const float* src, int Csrc, int H, int W,
                       const float* gw, const float* gb, int G) {
        dim3 g(H * W / 32, Csrc / 32, NB);
        pack_gn_x_kernel<<<g, dim3(32, 8)>>>(src, xhi + (size_t)PADPIX * Csrc,
                                             xlo + (size_t)PADPIX * Csrc,
                                             Csrc, 0, Csrc, H, W, gw, gb, G);
    };
    auto iwt_pack = [&](const float* src, __nv_bfloat16* dh, __nv_bfloat16* dl,
                        int C, int h, int w, int c_off, int Cdst,
                        const float* gw, const float* gb, int G) {
        dim3 g(h * w / 32, C / 32, NB);
        iwt_pack_kernel<<<g, dim3(32, 8)>>>(src, dh + (size_t)PADPIX * Cdst,
                                            dl + (size_t)PADPIX * Cdst, C, h, w, c_off, Cdst,
                                            gw, gb, G);
    };
    auto run_mma = [&](const __nv_bfloat16* Xh, const __nv_bfloat16* Xl,
                       const float* b, const float* skip, float* out,
                       int Cin, int Cout, int H, int W) {
        dim3 g(ntiles_of(H, W), (Cout + 127) / 128);
        conv_mma_kernel<<<g, 256, GEMM_SMEM>>>(whi, wlo, Xh + (size_t)PADPIX * Cin,
                                               Xl + (size_t)PADPIX * Cin, b, skip, out,
                                               Cin, Cout, H, W, 1);
    };
    auto gn_sr = [&](const float* xp, int C, int HW, int G) {
        int S = 2048 / (NB * G); if (S < 1) S = 1; if (S > 32) S = 32;
        gn_stats_kernel<<<NB * G * S, 256>>>(xp, C, HW, G, S);
        if (S > 1) gn_reduce_kernel<<<NB * G, 32>>>(S, (C / G) * HW);
    };

    // clear the persistent decoder concat buffers (written across encoder+decoder)
    {
        size_t b2 = (size_t)(2 * PADPIX + ntiles_of(32, 32) * 256) * 512 * sizeof(__nv_bfloat16);
        size_t b3 = (size_t)(2 * PADPIX + ntiles_of(64, 64) * 256) * 128 * sizeof(__nv_bfloat16);
        cudaMemsetAsync(xh2, 0, b2); cudaMemsetAsync(xl2, 0, b2);
        cudaMemsetAsync(xh3, 0, b3); cudaMemsetAsync(xl3, 0, b3);
    }

    // ---------------- encoder ----------------
    wt_kernel<<<blocks_for((size_t)NB * 3 * 128 * 128), 256>>>(x, t0, 3, 256, 256);
    ws_kernel<<<16, 256>>>(conv1_w, wsw, 12 * 9);
    conv3x3_c16_kernel<<<dim3(64, 1, NB), 256>>>(t0, wsw, conv1_b, nullptr, c1, 12, 16, 128, 128, 1,
                                                 nullptr, nullptr, 1);
    // c1: GN fused into wt_pack; normalized c1 written back in place (needed by copy_ch)
    gn_sr(c1, 16, 128 * 128, 2);
    prep_w(conv2_w, 64, 64);
    clear_x(64, 64, 64);
    wt_pack_kernel<<<blocks_for((size_t)NB * 16 * 64 * 64), 256>>>(
        c1, c1, nullptr, xhi + (size_t)PADPIX * 64, xlo + (size_t)PADPIX * 64,
        16, 128, 128, gn1_w, gn1_b, 2, nullptr, nullptr, 0, 0);
    run_mma(xhi, xlo, conv2_b, nullptr, c2, 64, 64, 64, 64);

    // c2: GN fused; normalized c2 ALSO packed straight into convd3's concat (xh3, ch 0-63)
    gn_sr(c2, 64, 64 * 64, 8);
    prep_w(conv3_w, 256, 256);
    clear_x(256, 32, 32);
    wt_pack_kernel<<<blocks_for((size_t)NB * 64 * 32 * 32), 256>>>(
        c2, nullptr, nullptr, xhi + (size_t)PADPIX * 256, xlo + (size_t)PADPIX * 256,
        64, 64, 64, gn2_w, gn2_b, 8,
        xh3 + (size_t)PADPIX * 128, xl3 + (size_t)PADPIX * 128, 0, 128);
    run_mma(xhi, xlo, conv3_b, nullptr, c3, 256, 256, 32, 32);

    // c3: GN fused; normalized c3 ALSO packed into convd4's concat (xh2, ch 0-255); w4 fp32 out
    gn_sr(c3, 256, 32 * 32, 32);
    prep_w(conv4_w, 1024, 1024);
    clear_x(1024, 16, 16);
    wt_pack_kernel<<<blocks_for((size_t)NB * 256 * 16 * 16), 256>>>(
        c3, nullptr, w4, xhi + (size_t)PADPIX * 1024, xlo + (size_t)PADPIX * 1024,
        256, 32, 32, gn3_w, gn3_b, 32,
        xh2 + (size_t)PADPIX * 512, xl2 + (size_t)PADPIX * 512, 0, 512);
    run_mma(xhi, xlo, conv4_b, nullptr, t0, 1024, 1024, 16, 16);

    gn_sr(t0, 1024, 256, 128);
    pack_gn(t0, 1024, 16, 16, gn4_w, gn4_b, 128);
    run_mma(xhi, xlo, conv4_b, nullptr, t1, 1024, 1024, 16, 16);

    gn_sr(t1, 1024, 256, 128);
    pack_gn(t1, 1024, 16, 16, gn4_w, gn4_b, 128);
    run_mma(xhi, xlo, conv4_b, w4, t0, 1024, 1024, 16, 16);   // ic4 = lrelu(conv + w4)

    // ---------------- decoder ----------------
    // convd4: concat buffer xh2 already holds c3 half; add iwt(ic4) half
    prep_w(convd4_w, 512, 256);
    iwt_pack(t0, xh2, xl2, 256, 16, 16, 256, 512, nullptr, nullptr, 1);
    run_mma(xh2, xl2, convd4_b, nullptr, t1, 512, 256, 32, 32);

    // convd3: concat buffer xh3 already holds c2 half; GN(ic3) fused into iwt_pack
    gn_sr(t1, 256, 32 * 32, 32);
    prep_w(convd3_w, 128, 64);
    iwt_pack(t1, xh3, xl3, 64, 32, 32, 64, 128, gn3_w, gn3_b, 32);
    run_mma(xh3, xl3, convd3_b, nullptr, t0, 128, 64, 64, 64);

    // level2 fp32 path: GN(ic2) fused into iwt_kernel
    gn_sr(t0, 64, 64 * 64, 8);
    iwt_kernel<<<blocks_for((size_t)NB * 16 * 64 * 64), 256>>>(
        t0, big, 16, 64, 64, 16, 32, gn2_w, gn2_b, 8);
    copy_ch_kernel<<<blocks_for((size_t)NB * 16 * 16384), 256>>>(c1, big, 16, 128 * 128, 32, 0);
    ws_kernel<<<16, 256>>>(convd2_w, wsw, 32 * 9);
    conv3x3_c16_kernel<<<dim3(64, 1, NB), 256>>>(big, wsw, convd2_b, nullptr, t1, 32, 16, 128, 128, 1,
                                                 nullptr, nullptr, 1);
    // ic1 raw in t1; GN fused into convd1's input load
    gn_sr(t1, 16, 128 * 128, 2);
    ws_kernel<<<12, 256>>>(convd1_w, wsw, 16 * 9);
    conv3x3_c16_kernel<<<dim3(64, 1, NB), 256>>>(t1, wsw, convd1_b, nullptr, t0, 16, 12, 128, 128, 1,
                                                 gn1_w, gn1_b, 2);

    iwt_kernel<<<blocks_for((size_t)NB * 3 * 128 * 128), 256>>>(
        t0, t1, 3, 128, 128, 0, 3, nullptr, nullptr, 1);
    ws_kernel<<<2, 256>>>(final_w, wsw, 3);
    final_kernel<<<blocks_for((size_t)NB * 256 * 256), 256>>>(t1, wsw, (float*)d_out, 256 * 256);
}

// round 17
// speedup vs baseline: 1.0461x; 1.0461x over previous
#include <cuda_runtime.h>
#include <cuda_bf16.h>
#include <math.h>
#include <stdint.h>

#define NB 16
#define PADPIX 256
#define GEMM_HDR 1024
#define STAGE_BYTES 98304  // Ahi16K+Alo16K+Bhi32K+Blo32K
#define GEMM_SMEM (GEMM_HDR + 2 * STAGE_BYTES)

// tcgen05 is arch-SPECIFIC: only emit it on the sm_103a/f pass, not compute_103.
#if (defined(__CUDA_ARCH_SPECIFIC__) && (__CUDA_ARCH_SPECIFIC__ == 1030)) || \
    (defined(__CUDA_ARCH_FAMILY_SPECIFIC__) && (__CUDA_ARCH_FAMILY_SPECIFIC__ == 1030))
#define HAS_TCGEN05 1
#else
#define HAS_TCGEN05 0
#endif

__device__ float g_c1 [4194304];
__device__ float g_c2 [4194304];
__device__ float g_c3 [4194304];
__device__ float g_w4 [4194304];
__device__ float g_t0 [4194304];
__device__ float g_t1 [4194304];
__device__ float g_big[8388608];
__device__ float g_wsw[9437184];
__device__ float g_part[16384];
__device__ float g_mstats[4096];
__device__ __align__(1024) __nv_bfloat16 g_xhi[12582912];
__device__ __align__(1024) __nv_bfloat16 g_xlo[12582912];
__device__ __align__(1024) __nv_bfloat16 g_whi[9437184];
__device__ __align__(1024) __nv_bfloat16 g_wlo[9437184];

// ---------------- PTX helpers ----------------
__device__ __forceinline__ uint32_t smem_u32(const void* p) {
    uint32_t a;
    asm("{ .reg .u64 t; cvta.to.shared.u64 t, %1; cvt.u32.u64 %0, t; }" : "=r"(a) : "l"(p));
    return a;
}
__device__ __forceinline__ uint32_t elect_one() {
    uint32_t p;
    asm volatile("{\n\t.reg .pred p;\n\telect.sync _|p, 0xFFFFFFFF;\n\tselp.b32 %0, 1, 0, p;\n\t}" : "=r"(p));
    return p;
}
#define SWZ(off) ((off) ^ (((off) >> 3) & 0x70))
static constexpr uint64_t DESC_BASE =
    (uint64_t(2) << 61) | (uint64_t(1) << 46) | (uint64_t(64) << 32) | (uint64_t(1) << 16);
#define MK_DESC(a) (DESC_BASE | ((uint64_t)((a) >> 4) & 0x3FFF))

#define MBAR_INIT(a, c) asm volatile("mbarrier.init.shared.b64 [%0], %1;" :: "r"((uint32_t)(a)), "r"((uint32_t)(c)) : "memory")
#define MBAR_INVAL(a)   asm volatile("mbarrier.inval.shared.b64 [%0];" :: "r"((uint32_t)(a)) : "memory")
#define MBAR_WAIT(a, par) do { \
    uint32_t _m = (uint32_t)(a), _p = (uint32_t)(par), _d; \
    asm volatile("{\n\t.reg .pred p;\n\tmbarrier.try_wait.parity.acquire.cta.shared::cta.b64 p, [%1], %2;\n\tselp.b32 %0, 1, 0, p;\n\t}" \
        : "=r"(_d) : "r"(_m), "r"(_p) : "memory"); \
    if (!_d) { \
        asm volatile("{\n\t.reg .pred P1;\n\tWL_%=:\n\tmbarrier.try_wait.parity.acquire.cta.shared::cta.b64 P1, [%0], %1, 0x989680;\n\t@P1 bra.uni WD_%=;\n\tbra.uni WL_%=;\n\tWD_%=:\n\t}" \
            :: "r"(_m), "r"(_p) : "memory"); \
    } } while (0)

__device__ __forceinline__ void cp16(uint32_t dst, const void* src) {
    asm volatile("cp.async.cg.shared.global [%0], [%1], 16;" :: "r"(dst), "l"(src));
}

#if HAS_TCGEN05
#define TC_ALLOC(sa, n)  asm volatile("tcgen05.alloc.cta_group::1.sync.aligned.shared::cta.b32 [%0], %1;" :: "r"((uint32_t)(sa)), "r"((uint32_t)(n)) : "memory")
#define TC_DEALLOC(t, n) asm volatile("tcgen05.dealloc.cta_group::1.sync.aligned.b32 %0, %1;" :: "r"(t), "r"((uint32_t)(n)))
#define TC_COMMIT(mb)    asm volatile("tcgen05.commit.cta_group::1.mbarrier::arrive::one.shared::cluster.b64 [%0];" :: "r"((uint32_t)(mb)) : "memory")
#define TC_FENCE_AFTER()  asm volatile("tcgen05.fence::after_thread_sync;" ::: "memory")
#define TC_FENCE_BEFORE() asm volatile("tcgen05.fence::before_thread_sync;" ::: "memory")
#define TC_WAIT_LD()      asm volatile("tcgen05.wait::ld.sync.aligned;" ::: "memory")
#define FENCE_ASYNC()     asm volatile("fence.proxy.async.shared::cta;" ::: "memory")

#define TC_LD_X32(r, ta) \
    asm volatile("tcgen05.ld.sync.aligned.32x32b.x32.b32 " \
        "{%0,%1,%2,%3,%4,%5,%6,%7,%8,%9,%10,%11,%12,%13,%14,%15," \
        "%16,%17,%18,%19,%20,%21,%22,%23,%24,%25,%26,%27,%28,%29,%30,%31}, [%32];" \
        : "=r"((r)[0]),"=r"((r)[1]),"=r"((r)[2]),"=r"((r)[3]),"=r"((r)[4]),"=r"((r)[5]),"=r"((r)[6]),"=r"((r)[7]), \
          "=r"((r)[8]),"=r"((r)[9]),"=r"((r)[10]),"=r"((r)[11]),"=r"((r)[12]),"=r"((r)[13]),"=r"((r)[14]),"=r"((r)[15]), \
          "=r"((r)[16]),"=r"((r)[17]),"=r"((r)[18]),"=r"((r)[19]),"=r"((r)[20]),"=r"((r)[21]),"=r"((r)[22]),"=r"((r)[23]), \
          "=r"((r)[24]),"=r"((r)[25]),"=r"((r)[26]),"=r"((r)[27]),"=r"((r)[28]),"=r"((r)[29]),"=r"((r)[30]),"=r"((r)[31]) \
        : "r"(ta))

__device__ __forceinline__ void mma_ss(uint32_t d, uint64_t a, uint64_t b, uint32_t idesc, uint32_t acc) {
    asm volatile(
        "{\n\t.reg .pred p;\n\tsetp.ne.u32 p, %5, 0;\n\t"
        "tcgen05.mma.cta_group::1.kind::f16 [%0], %1, %2, %3, {%4, %4, %4, %4}, p;\n\t}"
        :: "r"(d), "l"(a), "l"(b), "r"(idesc), "r"(0u), "r"(acc) : "memory");
}
#define MMA_IDESC 0x8400490u  // f32 acc, bf16 x bf16, M=128, N=256
#endif // HAS_TCGEN05

// ---------------- pack kernels ----------------
__device__ __forceinline__ void store_hilo(__nv_bfloat16* hi, __nv_bfloat16* lo,
                                           size_t idx, float v) {
    __nv_bfloat16 h = __float2bfloat16(v);
    hi[idx] = h;
    lo[idx] = __float2bfloat16(v - __bfloat162float(h));
}

// Zero only the guard head/tail + 1-pixel border ring of each padded image.
// Interior pixels are fully overwritten by the pack kernels.
__global__ void border_clear_kernel(__nv_bfloat16* __restrict__ hi, __nv_bfloat16* __restrict__ lo,
                                    int Cin, int H, int W, int ntiles)
{
    int Wp = W + 2, Hp = H + 2, HpWp = Hp * Wp;
    int cg = Cin >> 3;
    int Ptot = 2 * PADPIX + ntiles * 256;
    size_t total = (size_t)Ptot * cg;
    uint4 z = make_uint4(0, 0, 0, 0);
    for (size_t idx = (size_t)blockIdx.x * blockDim.x + threadIdx.x; idx < total;
         idx += (size_t)gridDim.x * blockDim.x) {
        int c8 = (int)(idx % cg);
        int p = (int)(idx / cg);
        int border;
        if (p < PADPIX || p >= PADPIX + NB * HpWp) {
            border = 1;
        } else {
            int q = p - PADPIX;
            int r = q % HpWp;
            int y = r / Wp, x = r - y * Wp;
            border = (y == 0) | (y == Hp - 1) | (x == 0) | (x == Wp - 1);
        }
        if (border) {
            size_t off = (size_t)p * Cin + c8 * 8;
            *reinterpret_cast<uint4*>(hi + off) = z;
            *reinterpret_cast<uint4*>(lo + off) = z;
        }
    }
}

__global__ void pack_gn_x_kernel(const float* __restrict__ src,
                                 __nv_bfloat16* __restrict__ hi, __nv_bfloat16* __restrict__ lo,
                                 int Csrc, int c_off, int Cdst, int H, int W,
                                 const float* __restrict__ gamma, const float* __restrict__ beta,
                                 int G)
{
    __shared__ float tile[32][33];
    int n = blockIdx.z;
    int c0 = blockIdx.y * 32;
    int p0 = blockIdx.x * 32;
    int HW = H * W;
    for (int cc = threadIdx.y; cc < 32; cc += 8)
        tile[cc][threadIdx.x] = src[((size_t)(n * Csrc + c0 + cc)) * HW + p0 + threadIdx.x];
    __syncthreads();
    int c = c0 + threadIdx.x;
    float sc = 1.f, sh = 0.f;
    if (gamma) {
        int cpg = Csrc / G;
        int ng = n * G + c / cpg;
        float mean = g_mstats[ng * 2], inv = g_mstats[ng * 2 + 1];
        sc = inv * gamma[c];
        sh = beta[c] - mean * sc;
    }
    int Wp = W + 2, HpWp = (H + 2) * Wp;
    for (int pp = threadIdx.y; pp < 32; pp += 8) {
        int p = p0 + pp; int y = p / W, x = p - y * W;
        size_t row = (size_t)n * HpWp + (size_t)(y + 1) * Wp + (x + 1);
        float v = tile[threadIdx.x][pp] * sc + sh;
        store_hilo(hi, lo, row * Cdst + c_off + c, v);
    }
}

// Haar inverse straight into packed bf16, with optional fused GroupNorm on the
// 4C-channel input tensor (applied BEFORE the detail remap, matching gn->iwt).
__global__ void iwt_pack_kernel(const float* __restrict__ in,
                                __nv_bfloat16* __restrict__ hi, __nv_bfloat16* __restrict__ lo,
                                int C, int h, int w, int c_off, int Cdst,
                                const float* __restrict__ gamma, const float* __restrict__ beta,
                                int G)
{
    __shared__ float tile[4][32][33];
    int n = blockIdx.z;
    int c0 = blockIdx.y * 32;
    int p0 = blockIdx.x * 32;
    int hw = h * w;
    int C4 = 4 * C, cpg = gamma ? (C4 / G) : 1;
    for (int k = 0; k < 4; k++)
        for (int cc = threadIdx.y; cc < 32; cc += 8) {
            int ch = 4 * (c0 + cc) + k;
            float v = in[((size_t)(n * C4 + ch)) * hw + p0 + threadIdx.x];
            if (gamma) {
                int ng = n * G + ch / cpg;
                float mean = g_mstats[ng * 2], inv = g_mstats[ng * 2 + 1];
                v = (v - mean) * inv * gamma[ch] + beta[ch];
            }
            tile[k][cc][threadIdx.x] = v;
        }
    __syncthreads();
    int c = c_off + c0 + threadIdx.x;
    int Wp = 2 * w + 2, HpWp = (2 * h + 2) * Wp;
    for (int pp = threadIdx.y; pp < 32; pp += 8) {
        int p = p0 + pp; int i = p / w, j = p - i * w;
        float s0 = tile[0][threadIdx.x][pp];
        float s1 = 2.f * tile[1][threadIdx.x][pp] - 1.f;
        float s2 = 2.f * tile[2][threadIdx.x][pp] - 1.f;
        float s3 = 2.f * tile[3][threadIdx.x][pp] - 1.f;
        size_t r00 = (size_t)n * HpWp + (size_t)(2 * i + 1) * Wp + (2 * j + 1);
        store_hilo(hi, lo, r00 * Cdst + c,            s0 + 0.5f * ( s1 + s2 + s3));
        store_hilo(hi, lo, (r00 + 1) * Cdst + c,      s0 + 0.5f * ( s1 - s2 - s3));
        store_hilo(hi, lo, (r00 + Wp) * Cdst + c,     s0 + 0.5f * (-s1 + s2 - s3));
        store_hilo(hi, lo, (r00 + Wp + 1) * Cdst + c, s0 + 0.5f * (-s1 - s2 + s3));
    }
}

__global__ void ws_pack_kernel(const float* __restrict__ w,
                               __nv_bfloat16* __restrict__ hi, __nv_bfloat16* __restrict__ lo,
                               int Cin, int Cout)
{
    int f = blockIdx.x;
    int K = Cin * 9;
    const float* wf = w + (size_t)f * K;
    __shared__ float red[256];
    float s = 0.f;
    for (int i = threadIdx.x; i < K; i += 256) s += wf[i];
    red[threadIdx.x] = s; __syncthreads();
    for (int o = 128; o; o >>= 1) { if (threadIdx.x < o) red[threadIdx.x] += red[threadIdx.x + o]; __syncthreads(); }
    float mean = red[0] / (float)K;
    __syncthreads();
    float ss = 0.f;
    for (int i = threadIdx.x; i < K; i += 256) { float d = wf[i] - mean; ss += d * d; }
    red[threadIdx.x] = ss; __syncthreads();
    for (int o = 128; o; o >>= 1) { if (threadIdx.x < o) red[threadIdx.x] += red[threadIdx.x + o]; __syncthreads(); }
    float inv = 1.0f / (sqrtf(red[0] / (float)(K - 1)) + 1e-5f);
    for (int i = threadIdx.x; i < K; i += 256) {
        int ci = i / 9, tap = i - ci * 9;
        float v = (wf[i] - mean) * inv;
        store_hilo(hi, lo, (size_t)(tap * Cout + f) * Cin + ci, v);
    }
}

// Fused: optional GroupNorm (per-channel affine from g_mstats, written back
// in-place via `normed`) -> Haar forward -> bf16 hi/lo pack (+ optional fp32 wt out).
__global__ void wt_pack_kernel(const float* __restrict__ in, float* __restrict__ normed,
                               float* __restrict__ outf,
                               __nv_bfloat16* __restrict__ hi, __nv_bfloat16* __restrict__ lo,
                               int C, int H, int W,
                               const float* __restrict__ gamma, const float* __restrict__ beta,
                               int G)
{
    int h2 = H >> 1, w2 = W >> 1;
    int C4 = 4 * C;
    int Wp = w2 + 2, HpWp = (h2 + 2) * Wp;
    int cpg = gamma ? (C / G) : 1;
    size_t total = (size_t)NB * C * h2 * w2;
    for (size_t idx = (size_t)blockIdx.x * blockDim.x + threadIdx.x; idx < total;
         idx += (size_t)gridDim.x * blockDim.x) {
        int j = (int)(idx % w2); size_t t = idx / w2;
        int i = (int)(t % h2); t /= h2;
        int c = (int)(t % C); int n = (int)(t / C);
        size_t pb = ((size_t)(n * C + c) * H + 2 * i) * W + 2 * j;
        const float* p = in + pb;
        float a = p[0], b = p[1], cc = p[W], d = p[W + 1];
        if (gamma) {
            int ng = n * G + c / cpg;
            float mean = g_mstats[ng * 2], inv = g_mstats[ng * 2 + 1];
            float sc = inv * gamma[c], sh = beta[c] - mean * sc;
            a = a * sc + sh; b = b * sc + sh; cc = cc * sc + sh; d = d * sc + sh;
            if (normed) {
                float* q = normed + pb;
                q[0] = a; q[1] = b; q[W] = cc; q[W + 1] = d;
            }
        }
        float v0 = 0.25f * (a + b + cc + d);
        float v1 = 0.25f * (a + b - cc - d) + 0.5f;
        float v2 = 0.25f * (a - b + cc - d) + 0.5f;
        float v3 = 0.25f * (a - b - cc + d) + 0.5f;
        if (outf) {
            size_t cs = (size_t)h2 * w2;
            size_t ob = (((size_t)n * C4 + 4 * c) * h2 + i) * w2 + j;
            outf[ob] = v0; outf[ob + cs] = v1; outf[ob + 2 * cs] = v2; outf[ob + 3 * cs] = v3;
        }
        size_t row = (size_t)n * HpWp + (size_t)(i + 1) * Wp + (j + 1);
        size_t base = row * C4 + 4 * c;
        store_hilo(hi, lo, base + 0, v0);
        store_hilo(hi, lo, base + 1, v1);
        store_hilo(hi, lo, base + 2, v2);
        store_hilo(hi, lo, base + 3, v3);
    }
}

// ---------------- tcgen05 conv (implicit GEMM, 3-pass bf16 hi/lo) ----------------
__global__ void __launch_bounds__(256, 1) conv_mma_kernel(
    const __nv_bfloat16* __restrict__ Whi, const __nv_bfloat16* __restrict__ Wlo,
    const __nv_bfloat16* __restrict__ Xhi, const __nv_bfloat16* __restrict__ Xlo,
    const float* __restrict__ bias, const float* __restrict__ skip,
    float* __restrict__ out, int Cin, int Cout, int H, int W, int do_lrelu)
{
#if HAS_TCGEN05
    extern __shared__ char smem[];
    uint32_t sb = smem_u32(smem);
    int tid = threadIdx.x, wid = tid >> 5, lane = tid & 31;
    int Wp = W + 2, HpWp = (H + 2) * Wp;
    int Np = NB * HpWp;
    int px_base = blockIdx.x * 256;
    int co_base = blockIdx.y * 128;
    int kchunks = Cin >> 6;
    int n_chunks = 9 * kchunks;

    if (wid == 0) TC_ALLOC(sb + 0, 256);
    if (tid == 0) { MBAR_INIT(sb + 16, 1); MBAR_INIT(sb + 24, 1); }
    __syncthreads();
    uint32_t tmem;
    asm volatile("ld.shared.b32 %0, [%1];" : "=r"(tmem) : "r"(sb + 0));

    int r0 = tid >> 3, g = tid & 7;

    auto load_chunk = [&](int i) {
        uint32_t stage = sb + GEMM_HDR + (i & 1) * STAGE_BYTES;
        int tap = i / kchunks, kc = i - tap * kchunks;
        int shift = (tap / 3 - 1) * Wp + (tap % 3 - 1);
        const __nv_bfloat16* ah = Whi + (size_t)(tap * Cout + co_base) * Cin + kc * 64;
        const __nv_bfloat16* al = Wlo + (size_t)(tap * Cout + co_base) * Cin + kc * 64;
        const __nv_bfloat16* bh = Xhi + (size_t)(px_base + shift) * Cin + kc * 64;
        const __nv_bfloat16* bl = Xlo + (size_t)(px_base + shift) * Cin + kc * 64;
#pragma unroll
        for (int j = 0; j < 4; j++) {
            int row = r0 + 32 * j;
            uint32_t d = SWZ((uint32_t)(row * 128 + g * 16));
            cp16(stage + 0     + d, ah + (size_t)row * Cin + g * 8);
            cp16(stage + 16384 + d, al + (size_t)row * Cin + g * 8);
        }
#pragma unroll
        for (int j = 0; j < 8; j++) {
            int row = r0 + 32 * j;
            uint32_t d = SWZ((uint32_t)(row * 128 + g * 16));
            cp16(stage + 32768 + d, bh + (size_t)row * Cin + g * 8);
            cp16(stage + 65536 + d, bl + (size_t)row * Cin + g * 8);
        }
        asm volatile("cp.async.commit_group;" ::: "memory");
    };

    load_chunk(0);
    for (int i = 0; i < n_chunks; i++) {
        if (i + 1 < n_chunks) {
            if (i >= 1) MBAR_WAIT(sb + 16 + 8 * ((i + 1) & 1), ((i - 1) >> 1) & 1);
            load_chunk(i + 1);
            asm volatile("cp.async.wait_group 1;" ::: "memory");
        } else {
            asm volatile("cp.async.wait_group 0;" ::: "memory");
        }
        __syncthreads();
        if (wid == 0 && elect_one()) {
            FENCE_ASYNC();
            uint32_t stage = sb + GEMM_HDR + (i & 1) * STAGE_BYTES;
            uint64_t dAh = MK_DESC(stage), dAl = MK_DESC(stage + 16384);
            uint64_t dBh = MK_DESC(stage + 32768), dBl = MK_DESC(stage + 65536);
#pragma unroll
            for (int k = 0; k < 4; k++)
                mma_ss(tmem, dAh + 2 * k, dBh + 2 * k, MMA_IDESC, (i != 0 || k != 0) ? 1u : 0u);
#pragma unroll
            for (int k = 0; k < 4; k++)
                mma_ss(tmem, dAl + 2 * k, dBh + 2 * k, MMA_IDESC, 1u);
#pragma unroll
            for (int k = 0; k < 4; k++)
                mma_ss(tmem, dAh + 2 * k, dBl + 2 * k, MMA_IDESC, 1u);
            TC_COMMIT(sb + 16 + 8 * (i & 1));
        }
    }
    {
        int uses0 = (n_chunks + 1) >> 1, uses1 = n_chunks >> 1;
        MBAR_WAIT(sb + 16, (uses0 - 1) & 1);
        if (uses1 > 0) MBAR_WAIT(sb + 24, (uses1 - 1) & 1);
    }
    TC_FENCE_AFTER();

    // epilogue: warp w -> subpartition w&3; half w>>2 covers 4 of 8 col-blocks
    float* tsm = reinterpret_cast<float*>(smem + GEMM_HDR) + wid * (32 * 33);
    int HW = H * W;
    int sub = wid & 3, half = wid >> 2;
    float bl_lane = (co_base + sub * 32 + lane < Cout) ? bias[co_base + sub * 32 + lane] : 0.f;
    for (int cb2 = half * 4; cb2 < half * 4 + 4; cb2++) {
        uint32_t regs[32];
        TC_LD_X32(regs, tmem + cb2 * 32);
        TC_WAIT_LD();
#pragma unroll
        for (int c = 0; c < 32; c++) tsm[c * 33 + lane] = __uint_as_float(regs[c]);
        __syncwarp();
        int p = px_base + cb2 * 32 + lane;
        int valid = 0; size_t obase = 0;
        if (p < Np) {
            int n = p / HpWp; int rem = p - n * HpWp;
            int yp = rem / Wp; int xp = rem - yp * Wp;
            if ((unsigned)(yp - 1) < (unsigned)H && (unsigned)(xp - 1) < (unsigned)W) {
                valid = 1;
                obase = ((size_t)n * Cout * H + (yp - 1)) * W + (xp - 1);
            }
        }
#pragma unroll
        for (int r = 0; r < 32; r++) {
            int co = co_base + sub * 32 + r;
            float bv = __shfl_sync(0xFFFFFFFFu, bl_lane, r);
            if (co < Cout && valid) {
                float v = tsm[lane * 33 + r] + bv;
                size_t o = obase + (size_t)co * HW;
                if (skip) v += skip[o];
                if (do_lrelu) v = v > 0.f ? v : 0.2f * v;
                out[o] = v;
            }
        }
        __syncwarp();
    }
    TC_FENCE_BEFORE();
    __syncthreads();
    if (tid == 0) { MBAR_INVAL(sb + 16); MBAR_INVAL(sb + 24); }
    __syncthreads();
    if (wid == 0) TC_DEALLOC(tmem, 256);
#endif // HAS_TCGEN05
}

// ---------------- fp32 helper kernels ----------------
__global__ void ws_kernel(const float* __restrict__ w, float* __restrict__ out, int K)
{
    int f = blockIdx.x;
    const float* wf = w + (size_t)f * K;
    __shared__ float red[256];
    float s = 0.f;
    for (int i = threadIdx.x; i < K; i += 256) s += wf[i];
    red[threadIdx.x] = s; __syncthreads();
    for (int o = 128; o; o >>= 1) { if (threadIdx.x < o) red[threadIdx.x] += red[threadIdx.x + o]; __syncthreads(); }
    float mean = red[0] / (float)K;
    __syncthreads();
    float ss = 0.f;
    for (int i = threadIdx.x; i < K; i += 256) { float d = wf[i] - mean; ss += d * d; }
    red[threadIdx.x] = ss; __syncthreads();
    for (int o = 128; o; o >>= 1) { if (threadIdx.x < o) red[threadIdx.x] += red[threadIdx.x + o]; __syncthreads(); }
    float inv = 1.0f / (sqrtf(red[0] / (float)(K - 1)) + 1e-5f);
    for (int i = threadIdx.x; i < K; i += 256)
        out[(size_t)f * K + i] = (wf[i] - mean) * inv;
}

// S==1: finalize stats directly into g_mstats (skips the reduce launch).
__global__ void gn_stats_kernel(const float* __restrict__ x, int C, int HW, int G, int S)
{
    int gid = blockIdx.x;
    int ng = gid / S, sl = gid - (gid / S) * S;
    int n = ng / G, grp = ng % G;
    int cpg = C / G;
    int len = cpg * HW;
    int slice = (len + S - 1) / S;
    int start = sl * slice;
    int end = start + slice; if (end > len) end = len;
    size_t base = ((size_t)n * C + (size_t)grp * cpg) * HW;
    __shared__ float r1[256], r2[256];
    float s = 0.f, ss = 0.f;
    for (int i = start + threadIdx.x; i < end; i += 256) {
        float v = x[base + i]; s += v; ss += v * v;
    }
    r1[threadIdx.x] = s; r2[threadIdx.x] = ss; __syncthreads();
    for (int o = 128; o; o >>= 1) {
        if (threadIdx.x < o) { r1[threadIdx.x] += r1[threadIdx.x + o]; r2[threadIdx.x] += r2[threadIdx.x + o]; }
        __syncthreads();
    }
    if (threadIdx.x == 0) {
        if (S == 1) {
            float mean = r1[0] / (float)len;
            float var  = r2[0] / (float)len - mean * mean;
            g_mstats[ng * 2] = mean;
            g_mstats[ng * 2 + 1] = rsqrtf(var + 1e-5f);
        } else {
            g_part[gid * 2] = r1[0]; g_part[gid * 2 + 1] = r2[0];
        }
    }
}
__global__ void gn_reduce_kernel(int S, int len)
{
    int ng = blockIdx.x;
    float s = 0.f, ss = 0.f;
    for (int i = threadIdx.x; i < S; i += 32) {
        s  += g_part[(ng * S + i) * 2];
        ss += g_part[(ng * S + i) * 2 + 1];
    }
    for (int o = 16; o; o >>= 1) {
        s  += __shfl_down_sync(0xFFFFFFFFu, s, o);
        ss += __shfl_down_sync(0xFFFFFFFFu, ss, o);
    }
    if (threadIdx.x == 0) {
        float mean = s / (float)len;
        float var  = ss / (float)len - mean * mean;
        g_mstats[ng * 2] = mean;
        g_mstats[ng * 2 + 1] = rsqrtf(var + 1e-5f);
    }
}

__global__ void wt_kernel(const float* __restrict__ in, float* __restrict__ out, int C, int H, int W)
{
    int h2 = H >> 1, w2 = W >> 1;
    size_t total = (size_t)NB * C * h2 * w2;
    for (size_t idx = (size_t)blockIdx.x * blockDim.x + threadIdx.x; idx < total;
         idx += (size_t)gridDim.x * blockDim.x) {
        int j = (int)(idx % w2); size_t t = idx / w2;
        int i = (int)(t % h2); t /= h2;
        int c = (int)(t % C); int n = (int)(t / C);
        const float* p = in + ((size_t)(n * C + c) * H + 2 * i) * W + 2 * j;
        float a = p[0], b = p[1], cc = p[W], d = p[W + 1];
        size_t cs = (size_t)h2 * w2;
        size_t ob = (((size_t)n * 4 * C + 4 * c) * h2 + i) * w2 + j;
        out[ob]          = 0.25f * (a + b + cc + d);
        out[ob + cs]     = 0.25f * (a + b - cc - d) + 0.5f;
        out[ob + 2 * cs] = 0.25f * (a - b + cc - d) + 0.5f;
        out[ob + 3 * cs] = 0.25f * (a - b - cc + d) + 0.5f;
    }
}

// fp32 Haar inverse with optional fused GroupNorm on the 4C-channel input.
__global__ void iwt_kernel(const float* __restrict__ in, float* __restrict__ out,
                           int C, int h, int w, int c_off, int Cdst,
                           const float* __restrict__ gamma, const float* __restrict__ beta,
                           int G)
{
    size_t total = (size_t)NB * C * h * w;
    int C4 = 4 * C, cpg = gamma ? (C4 / G) : 1;
    for (size_t idx = (size_t)blockIdx.x * blockDim.x + threadIdx.x; idx < total;
         idx += (size_t)gridDim.x * blockDim.x) {
        int j = (int)(idx % w); size_t t = idx / w;
        int i = (int)(t % h); t /= h;
        int c = (int)(t % C); int n = (int)(t / C);
        size_t cs = (size_t)h * w;
        size_t ib = (((size_t)n * C4 + 4 * c) * h + i) * w + j;
        float sv[4];
#pragma unroll
        for (int k = 0; k < 4; k++) {
            float v = in[ib + k * cs];
            if (gamma) {
                int ch = 4 * c + k;
                int ng = n * G + ch / cpg;
                float mean = g_mstats[ng * 2], inv = g_mstats[ng * 2 + 1];
                v = (v - mean) * inv * gamma[ch] + beta[ch];
            }
            sv[k] = v;
        }
        float s0 = sv[0];
        float s1 = 2.f * sv[1] - 1.f;
        float s2 = 2.f * sv[2] - 1.f;
        float s3 = 2.f * sv[3] - 1.f;
        float* q = out + (((size_t)n * Cdst + c_off + c) * 2 * h + 2 * i) * 2 * w + 2 * j;
        q[0]         = s0 + 0.5f * ( s1 + s2 + s3);
        q[1]         = s0 + 0.5f * ( s1 - s2 - s3);
        q[2 * w]     = s0 + 0.5f * (-s1 + s2 - s3);
        q[2 * w + 1] = s0 + 0.5f * (-s1 - s2 + s3);
    }
}

// Fused final stage: iwt (12ch @128x128 -> 3ch @256x256) + 1x1 ws_conv (3->2), no bias.
__global__ void iwt_final_kernel(const float* __restrict__ in, const float* __restrict__ wf,
                                 float* __restrict__ out, int h, int w)
{
    size_t total = (size_t)NB * h * w;
    int H2 = 2 * h, W2 = 2 * w;
    size_t cs = (size_t)h * w;
    for (size_t idx = (size_t)blockIdx.x * blockDim.x + threadIdx.x; idx < total;
         idx += (size_t)gridDim.x * blockDim.x) {
        int j = (int)(idx % w); size_t t = idx / w;
        int i = (int)(t % h); int n = (int)(t / h);
        float px[3][4];
#pragma unroll
        for (int c = 0; c < 3; c++) {
            size_t ib = (((size_t)n * 12 + 4 * c) * h + i) * w + j;
            float s0 = in[ib];
            float s1 = 2.f * in[ib + cs]     - 1.f;
            float s2 = 2.f * in[ib + 2 * cs] - 1.f;
            float s3 = 2.f * in[ib + 3 * cs] - 1.f;
            px[c][0] = s0 + 0.5f * ( s1 + s2 + s3);
            px[c][1] = s0 + 0.5f * ( s1 - s2 - s3);
            px[c][2] = s0 + 0.5f * (-s1 + s2 - s3);
            px[c][3] = s0 + 0.5f * (-s1 - s2 + s3);
        }
        float w0 = wf[0], w1 = wf[1], w2 = wf[2], w3 = wf[3], w4 = wf[4], w5 = wf[5];
        size_t ob0 = ((size_t)(n * 2) * H2 + 2 * i) * W2 + 2 * j;
        size_t ob1 = ((size_t)(n * 2 + 1) * H2 + 2 * i) * W2 + 2 * j;
#pragma unroll
        for (int k = 0; k < 4; k++) {
            size_t off = (size_t)(k >> 1) * W2 + (k & 1);
            out[ob0 + off] = w0 * px[0][k] + w1 * px[1][k] + w2 * px[2][k];
            out[ob1 + off] = w3 * px[0][k] + w4 * px[1][k] + w5 * px[2][k];
        }
    }
}

__global__ void copy_ch_kernel(const float* __restrict__ src, float* __restrict__ dst,
                               int C, int HW, int Cdst, int c_off)
{
    size_t total = (size_t)NB * C * HW;
    for (size_t idx = (size_t)blockIdx.x * blockDim.x + threadIdx.x; idx < total;
         idx += (size_t)gridDim.x * blockDim.x) {
        int p = (int)(idx % HW); size_t t = idx / HW;
        int c = (int)(t % C); int n = (int)(t / C);
        dst[((size_t)n * Cdst + c_off + c) * HW + p] = src[idx];
    }
}

// fp32 direct conv, 16-co tile; optional fused GroupNorm affine on the INPUT.
__global__ __launch_bounds__(256) void conv3x3_c16_kernel(
    const float* __restrict__ in, const float* __restrict__ wgt,
    const float* __restrict__ bias, const float* __restrict__ skip,
    float* __restrict__ out, int Cin, int Cout, int H, int W, int do_lrelu,
    const float* __restrict__ gamma, const float* __restrict__ beta, int G)
{
    __shared__ __align__(16) float s_in[4][18][18];
    __shared__ __align__(16) float s_w[4][9][16];
    int tiles_x = W >> 4;
    int tx0 = (blockIdx.x % tiles_x) << 4;
    int ty0 = (blockIdx.x / tiles_x) << 4;
    int n = blockIdx.z;
    int tx = threadIdx.x;
    int cog8 = (tx >> 7) << 3;
    int pid  = tx & 127;
    int prow = pid >> 3;
    int pcol = (pid & 7) << 1;
    int cpg = gamma ? (Cin / G) : 1;

    float acc[8][2];
#pragma unroll
    for (int r = 0; r < 8; r++) { acc[r][0] = 0.f; acc[r][1] = 0.f; }

    for (int cc = 0; cc < Cin; cc += 4) {
        for (int idx = tx; idx < 4 * 9 * 16; idx += 256) {
            int co = idx & 15;
            int tap = (idx >> 4) % 9;
            int ci = (idx >> 4) / 9;
            float v = 0.f;
            if (co < Cout && cc + ci < Cin)
                v = wgt[((size_t)co * Cin + cc + ci) * 9 + tap];
            s_w[ci][tap][co] = v;
        }
        for (int idx = tx; idx < 4 * 18 * 18; idx += 256) {
            int ix = idx % 18; int t = idx / 18;
            int iy = t % 18;  int ci = t / 18;
            int gy = ty0 + iy - 1, gx = tx0 + ix - 1;
            float v = 0.f;
            if (cc + ci < Cin && gy >= 0 && gy < H && gx >= 0 && gx < W) {
                v = in[((size_t)(n * Cin + cc + ci) * H + gy) * W + gx];
                if (gamma) {
                    int ch = cc + ci;
                    int ng = n * G + ch / cpg;
                    float mean = g_mstats[ng * 2], inv = g_mstats[ng * 2 + 1];
                    v = (v - mean) * inv * gamma[ch] + beta[ch];
                }
            }
            s_in[ci][iy][ix] = v;
        }
        __syncthreads();
#pragma unroll
        for (int ci = 0; ci < 4; ci++)
#pragma unroll
            for (int dy = 0; dy < 3; dy++)
#pragma unroll
                for (int dx = 0; dx < 3; dx++) {
                    float x0 = s_in[ci][prow + dy][pcol + dx];
                    float x1 = s_in[ci][prow + dy][pcol + dx + 1];
                    const float* wp = &s_w[ci][dy * 3 + dx][cog8];
                    float4 wa = *reinterpret_cast<const float4*>(wp);
                    float4 wb = *reinterpret_cast<const float4*>(wp + 4);
                    float wv[8] = {wa.x, wa.y, wa.z, wa.w, wb.x, wb.y, wb.z, wb.w};
#pragma unroll
                    for (int r = 0; r < 8; r++) {
                        acc[r][0] = fmaf(wv[r], x0, acc[r][0]);
                        acc[r][1] = fmaf(wv[r], x1, acc[r][1]);
                    }
                }
        __syncthreads();
    }
    int oy = ty0 + prow;
#pragma unroll
    for (int r = 0; r < 8; r++) {
        int co = cog8 + r;
        if (co < Cout) {
            float b = bias ? bias[co] : 0.f;
            size_t ob = ((size_t)(n * Cout + co) * H + oy) * W + tx0 + pcol;
#pragma unroll
            for (int p = 0; p < 2; p++) {
                float v = acc[r][p] + b;
                if (skip) v += skip[ob + p];
                if (do_lrelu) v = v > 0.f ? v : 0.2f * v;
                out[ob + p] = v;
            }
        }
    }
}

// ---------------- host ----------------
static inline int blocks_for(size_t n) { return (int)((n + 255) / 256); }

extern "C" void kernel_launch(void* const* d_in, const int* in_sizes, int n_in,
                              void* d_out, int out_size)
{
    const float* x        = (const float*)d_in[0];
    const float* conv1_w  = (const float*)d_in[1];  const float* conv1_b  = (const float*)d_in[2];
    const float* conv2_w  = (const float*)d_in[3];  const float* conv2_b  = (const float*)d_in[4];
    const float* conv3_w  = (const float*)d_in[5];  const float* conv3_b  = (const float*)d_in[6];
    const float* conv4_w  = (const float*)d_in[7];  const float* conv4_b  = (const float*)d_in[8];
    const float* convd1_w = (const float*)d_in[9];  const float* convd1_b = (const float*)d_in[10];
    const float* convd2_w = (const float*)d_in[11]; const float* convd2_b = (const float*)d_in[12];
    const float* convd3_w = (const float*)d_in[13]; const float* convd3_b = (const float*)d_in[14];
    const float* convd4_w = (const float*)d_in[15]; const float* convd4_b = (const float*)d_in[16];
    const float* final_w  = (const float*)d_in[17];
    const float* gn1_w = (const float*)d_in[18]; const float* gn1_b = (const float*)d_in[19];
    const float* gn2_w = (const float*)d_in[20]; const float* gn2_b = (const float*)d_in[21];
    const float* gn3_w = (const float*)d_in[22]; const float* gn3_b = (const float*)d_in[23];
    const float* gn4_w = (const float*)d_in[24]; const float* gn4_b = (const float*)d_in[25];

    float *c1, *c2, *c3, *w4, *t0, *t1, *big, *wsw;
    __nv_bfloat16 *xhi, *xlo, *whi, *wlo;
    cudaGetSymbolAddress((void**)&c1,  g_c1);
    cudaGetSymbolAddress((void**)&c2,  g_c2);
    cudaGetSymbolAddress((void**)&c3,  g_c3);
    cudaGetSymbolAddress((void**)&w4,  g_w4);
    cudaGetSymbolAddress((void**)&t0,  g_t0);
    cudaGetSymbolAddress((void**)&t1,  g_t1);
    cudaGetSymbolAddress((void**)&big, g_big);
    cudaGetSymbolAddress((void**)&wsw, g_wsw);
    cudaGetSymbolAddress((void**)&xhi, g_xhi);
    cudaGetSymbolAddress((void**)&xlo, g_xlo);
    cudaGetSymbolAddress((void**)&whi, g_whi);
    cudaGetSymbolAddress((void**)&wlo, g_wlo);

    cudaFuncSetAttribute(conv_mma_kernel, cudaFuncAttributeMaxDynamicSharedMemorySize, GEMM_SMEM);

    auto ntiles_of = [](int H, int W) { return (NB * (H + 2) * (W + 2) + 255) / 256; };
    auto prep_w = [&](const float* w, int Cin, int Cout) {
        ws_pack_kernel<<<Cout, 256>>>(w, whi, wlo, Cin, Cout);
    };
    auto clear_x = [&](int Cin, int H, int W) {
        int nt = ntiles_of(H, W);
        size_t total = (size_t)(2 * PADPIX + nt * 256) * (Cin / 8);
        border_clear_kernel<<<blocks_for(total), 256>>>(xhi, xlo, Cin, H, W, nt);
    };
    auto pack_plain = [&](const float* src, int Csrc, int c_off, int Cdst, int H, int W) {
        dim3 g(H * W / 32, Csrc / 32, NB);
        pack_gn_x_kernel<<<g, dim3(32, 8)>>>(src, xhi + (size_t)PADPIX * Cdst,
                                             xlo + (size_t)PADPIX * Cdst,
                                             Csrc, c_off, Cdst, H, W, nullptr, nullptr, 1);
    };
    auto pack_gn = [&](const float* src, int Csrc, int H, int W,
                       const float* gw, const float* gb, int G) {
        dim3 g(H * W / 32, Csrc / 32, NB);
        pack_gn_x_kernel<<<g, dim3(32, 8)>>>(src, xhi + (size_t)PADPIX * Csrc,
                                             xlo + (size_t)PADPIX * Csrc,
                                             Csrc, 0, Csrc, H, W, gw, gb, G);
    };
    auto iwt_pack = [&](const float* src, int C, int h, int w, int c_off, int Cdst,
                        const float* gw, const float* gb, int G) {
        dim3 g(h * w / 32, C / 32, NB);
        iwt_pack_kernel<<<g, dim3(32, 8)>>>(src, xhi + (size_t)PADPIX * Cdst,
                                            xlo + (size_t)PADPIX * Cdst, C, h, w, c_off, Cdst,
                                            gw, gb, G);
    };
    auto wt_pack_gn = [&](float* src, float* normed, float* outf, int C, int H, int W,
                          const float* gw, const float* gb, int G) {
        int C4 = 4 * C;
        wt_pack_kernel<<<blocks_for((size_t)NB * C * (H / 2) * (W / 2)), 256>>>(
            src, normed, outf, xhi + (size_t)PADPIX * C4, xlo + (size_t)PADPIX * C4,
            C, H, W, gw, gb, G);
    };
    auto run_mma = [&](const float* b, const float* skip, float* out,
                       int Cin, int Cout, int H, int W) {
        dim3 g(ntiles_of(H, W), (Cout + 127) / 128);
        conv_mma_kernel<<<g, 256, GEMM_SMEM>>>(whi, wlo, xhi + (size_t)PADPIX * Cin,
                                               xlo + (size_t)PADPIX * Cin, b, skip, out,
                                               Cin, Cout, H, W, 1);
    };
    auto gn_sr = [&](const float* xp, int C, int HW, int G) {
        int S = 2048 / (NB * G); if (S < 1) S = 1; if (S > 32) S = 32;
        gn_stats_kernel<<<NB * G * S, 256>>>(xp, C, HW, G, S);
        if (S > 1) gn_reduce_kernel<<<NB * G, 32>>>(S, (C / G) * HW);
    };

    // ---------------- encoder ----------------
    wt_kernel<<<blocks_for((size_t)NB * 3 * 128 * 128), 256>>>(x, t0, 3, 256, 256);
    ws_kernel<<<16, 256>>>(conv1_w, wsw, 12 * 9);
    conv3x3_c16_kernel<<<dim3(64, 1, NB), 256>>>(t0, wsw, conv1_b, nullptr, c1, 12, 16, 128, 128, 1,
                                                 nullptr, nullptr, 1);
    // c1/c2/c3: GN fused into wt_pack; normalized value written back IN PLACE
    // (the decoder concats re-read them and need the normalized values).
    gn_sr(c1, 16, 128 * 128, 2);
    prep_w(conv2_w, 64, 64);
    clear_x(64, 64, 64);
    wt_pack_gn(c1, c1, nullptr, 16, 128, 128, gn1_w, gn1_b, 2);
    run_mma(conv2_b, nullptr, c2, 64, 64, 64, 64);

    gn_sr(c2, 64, 64 * 64, 8);
    prep_w(conv3_w, 256, 256);
    clear_x(256, 32, 32);
    wt_pack_gn(c2, c2, nullptr, 64, 64, 64, gn2_w, gn2_b, 8);
    run_mma(conv3_b, nullptr, c3, 256, 256, 32, 32);

    gn_sr(c3, 256, 32 * 32, 32);
    prep_w(conv4_w, 1024, 1024);
    clear_x(1024, 16, 16);
    wt_pack_gn(c3, c3, w4, 256, 32, 32, gn3_w, gn3_b, 32);
    run_mma(conv4_b, nullptr, t0, 1024, 1024, 16, 16);

    gn_sr(t0, 1024, 256, 128);
    pack_gn(t0, 1024, 16, 16, gn4_w, gn4_b, 128);
    run_mma(conv4_b, nullptr, t1, 1024, 1024, 16, 16);

    gn_sr(t1, 1024, 256, 128);
    pack_gn(t1, 1024, 16, 16, gn4_w, gn4_b, 128);
    run_mma(conv4_b, w4, t0, 1024, 1024, 16, 16);   // ic4 = lrelu(conv + w4)

    // ---------------- decoder ----------------
    prep_w(convd4_w, 512, 256);
    clear_x(512, 32, 32);
    iwt_pack(t0, 256, 16, 16, 256, 512, nullptr, nullptr, 1);
    pack_plain(c3, 256, 0, 512, 32, 32);
    run_mma(convd4_b, nullptr, t1, 512, 256, 32, 32);

    gn_sr(t1, 256, 32 * 32, 32);
    prep_w(convd3_w, 128, 64);
    clear_x(128, 64, 64);
    iwt_pack(t1, 64, 32, 32, 64, 128, gn3_w, gn3_b, 32);
    pack_plain(c2, 64, 0, 128, 64, 64);
    run_mma(convd3_b, nullptr, t0, 128, 64, 64, 64);

    gn_sr(t0, 64, 64 * 64, 8);
    iwt_kernel<<<blocks_for((size_t)NB * 16 * 64 * 64), 256>>>(
        t0, big, 16, 64, 64, 16, 32, gn2_w, gn2_b, 8);
    copy_ch_kernel<<<blocks_for((size_t)NB * 16 * 16384), 256>>>(c1, big, 16, 128 * 128, 32, 0);
    ws_kernel<<<16, 256>>>(convd2_w, wsw, 32 * 9);
    conv3x3_c16_kernel<<<dim3(64, 1, NB), 256>>>(big, wsw, convd2_b, nullptr, t1, 32, 16, 128, 128, 1,
                                                 nullptr, nullptr, 1);
    // ic1 raw in t1; GN fused into convd1's input load
    gn_sr(t1, 16, 128 * 128, 2);
    ws_kernel<<<12, 256>>>(convd1_w, wsw, 16 * 9);
    conv3x3_c16_kernel<<<dim3(64, 1, NB), 256>>>(t1, wsw, convd1_b, nullptr, t0, 16, 12, 128, 128, 1,
                                                 gn1_w, gn1_b, 2);

    // fused: iwt(iw1) + final 1x1 ws_conv straight to d_out
    ws_kernel<<<2, 256>>>(final_w, wsw, 3);
    iwt_final_kernel<<<blocks_for((size_t)NB * 128 * 128), 256>>>(
        t0, wsw, (float*)d_out, 128, 128);
}